// round 11
// baseline (speedup 1.0000x reference)
#include <cuda_runtime.h>
#include <cuda_bf16.h>
#include <cstdint>

// ---------------- problem constants ----------------
#define N_SPK 8192
#define M_UTT 10
#define D_EMB 128
#define CLAMP_MIN 1e-6f

// int8 quantization: q = round(v * 127), cos = acc / 127^2
#define QSCALE 127.0f
#define QINV (1.0f / (QSCALE * QSCALE))      // 1/16129

// ---------------- gemm tiling ----------------
#define TM 128                        // rows per CTA
#define TN 256                        // cols per tile
#define COLS_PER_CTA 4096             // grid.x = 2 column halves
#define NTILES (COLS_PER_CTA / TN)    // 16
#define GTHREADS 256                  // 8 warps: 2(M) x 4(N), warp tile 64x64

#define ROW_BYTES 128                 // 128 int8
#define A_BYTES   (128 * ROW_BYTES)   // 16 KB
#define B_BYTES   (256 * ROW_BYTES)   // 32 KB per buffer
#define SMEM_TOTAL (A_BYTES + 2 * B_BYTES)   // 80 KB

// ---------------- device scratch ----------------
__device__ __align__(16) uint32_t g_lq[N_SPK * 32];   // int8x4 packed, row=128B
__device__ __align__(16) uint32_t g_cq[N_SPK * 32];
__device__ float g_part[2][N_SPK];
__device__ float g_diag[N_SPK];

// ---------------- helpers ----------------
__device__ __forceinline__ uint32_t smem_u32(const void* p) {
    uint32_t a;
    asm("{ .reg .u64 t; cvta.to.shared.u64 t, %1; cvt.u32.u64 %0, t; }" : "=r"(a) : "l"(p));
    return a;
}
__device__ __forceinline__ void cp16(uint32_t dst, const void* src) {
    asm volatile("cp.async.cg.shared.global [%0], [%1], 16;" :: "r"(dst), "l"(src) : "memory");
}
#define CP_COMMIT() asm volatile("cp.async.commit_group;" ::: "memory")
#define CP_WAIT0()  asm volatile("cp.async.wait_group 0;" ::: "memory")

#define LDMX4(r0, r1, r2, r3, addr)                                            \
    asm volatile("ldmatrix.sync.aligned.m8n8.x4.shared.b16 {%0,%1,%2,%3}, [%4];" \
                 : "=r"(r0), "=r"(r1), "=r"(r2), "=r"(r3) : "r"(addr))

__device__ __forceinline__ void mma_s8(int4& c, uint32_t a0, uint32_t a1,
                                       uint32_t a2, uint32_t a3,
                                       uint32_t b0, uint32_t b1) {
    asm volatile(
        "mma.sync.aligned.m16n8k32.row.col.s32.s8.s8.s32 "
        "{%0,%1,%2,%3}, {%4,%5,%6,%7}, {%8,%9}, {%0,%1,%2,%3};"
        : "+r"(c.x), "+r"(c.y), "+r"(c.z), "+r"(c.w)
        : "r"(a0), "r"(a1), "r"(a2), "r"(a3), "r"(b0), "r"(b1));
}

__device__ __forceinline__ float ex2f(float x) {
    float r; asm("ex2.approx.ftz.f32 %0, %1;" : "=f"(r) : "f"(x)); return r;
}
__device__ __forceinline__ float lg2f(float x) {
    float r; asm("lg2.approx.f32 %0, %1;" : "=f"(r) : "f"(x)); return r;
}
__device__ __forceinline__ uint32_t pack4(int a, int b, int c, int d) {
    return (uint32_t)(a & 0xFF) | ((uint32_t)(b & 0xFF) << 8) |
           ((uint32_t)(c & 0xFF) << 16) | ((uint32_t)(d & 0xFF) << 24);
}

// ---------------------------------------------------------------------------
// Kernel 1: centroids + normalization + int8 quantization (round-to-nearest).
// One warp per speaker, lane covers 4 dims via float4.
// ---------------------------------------------------------------------------
__global__ void __launch_bounds__(256) prep_kernel(const float* __restrict__ x) {
    const int lane = threadIdx.x & 31;
    const int n = blockIdx.x * 8 + (threadIdx.x >> 5);
    const float4* xs = (const float4*)(x + (size_t)n * (M_UTT * D_EMB));

    float4 c = make_float4(0.f, 0.f, 0.f, 0.f);
    float4 l;
#pragma unroll
    for (int m = 0; m < M_UTT; m++) {
        float4 v = xs[m * 32 + lane];
        c.x += v.x; c.y += v.y; c.z += v.z; c.w += v.w;
        if (m == M_UTT - 1) l = v;
    }
    c.x *= 0.1f; c.y *= 0.1f; c.z *= 0.1f; c.w *= 0.1f;

    float sc = c.x * c.x + c.y * c.y + c.z * c.z + c.w * c.w;
    float sl = l.x * l.x + l.y * l.y + l.z * l.z + l.w * l.w;
#pragma unroll
    for (int o = 16; o; o >>= 1) {
        sc += __shfl_xor_sync(0xffffffffu, sc, o);
        sl += __shfl_xor_sync(0xffffffffu, sl, o);
    }
    const float rc = rsqrtf(sc) * QSCALE, rl = rsqrtf(sl) * QSCALE;

    g_cq[n * 32 + lane] = pack4(__float2int_rn(c.x * rc), __float2int_rn(c.y * rc),
                                __float2int_rn(c.z * rc), __float2int_rn(c.w * rc));
    g_lq[n * 32 + lane] = pack4(__float2int_rn(l.x * rl), __float2int_rn(l.y * rl),
                                __float2int_rn(l.z * rl), __float2int_rn(l.w * rl));
}

// ---------------------------------------------------------------------------
// Kernel 2: int8 mma.sync GEMM (m16n8k32), warp tile 64x64, ldmatrix loads.
// Grid (2, 64), 256 threads. Smem: A 16KB + B double buffer 2x32KB = 80KB.
// Swizzle: 16B chunk c (0..7) of row r stored at c ^ (r & 7).
// ---------------------------------------------------------------------------
__global__ void __launch_bounds__(GTHREADS, 1) gemm_lse_kernel(
    const float* __restrict__ wp, const float* __restrict__ bp) {
    extern __shared__ char smem[];
    const uint32_t sb = smem_u32(smem);

    const int tid = threadIdx.x;
    const int wid = tid >> 5, lane = tid & 31;
    const int warp_m = wid >> 2;          // 0..1 : 64-row stripe
    const int warp_n = wid & 3;           // 0..3 : 64-col stripe
    const int gid = lane >> 2;            // 0..7
    const int tid4 = lane & 3;

    const int h = blockIdx.x;
    const int rb = blockIdx.y;
    const int rowBase = rb * TM;
    const int colBase = h * COLS_PER_CTA;
    const int tdiag = ((rb >> 5) == h) ? ((rb - h * 32) >> 1) : -1;
    const int dOff = (rb & 1) * 128;      // local col offset of diag block

    const float w = *wp, b = *bp;
    const float LOG2E = 1.44269504f;
    const float wl = w * LOG2E * QINV;    // fma multiplier on raw int acc
    const float bl = b * LOG2E;
    const float dm = w * QINV;
    const float FCLAMP = CLAMP_MIN * QSCALE * QSCALE;   // clamp on raw acc

    // ---- async-load A stripe (4 chunks/thr) + B tile 0 (8 chunks/thr) ----
    const uint4* A4 = (const uint4*)g_lq;   // 8 chunks per 128B row
    const uint4* B4 = (const uint4*)g_cq;
#pragma unroll
    for (int p = 0; p < 4; p++) {
        int idx = p * GTHREADS + tid;
        int r = idx >> 3, c = idx & 7;
        cp16(sb + (uint32_t)(r * ROW_BYTES + ((c ^ (r & 7)) << 4)),
             &A4[(rowBase + r) * 8 + c]);
    }
#pragma unroll
    for (int p = 0; p < 8; p++) {
        int idx = p * GTHREADS + tid;
        int r = idx >> 3, c = idx & 7;
        cp16(sb + A_BYTES + (uint32_t)(r * ROW_BYTES + ((c ^ (r & 7)) << 4)),
             &B4[(colBase + r) * 8 + c]);
    }
    CP_COMMIT();
    CP_WAIT0();
    __syncthreads();

    // ---- ldmatrix lane-address precompute (identical mapping to bf16 case;
    //      each "b16" element = 2 int8, one k-step now covers 32 bytes) ----
    uint32_t aBase[4]; uint32_t aSw[4];
    const int aK = lane >> 4;             // 16B k-chunk select
#pragma unroll
    for (int i = 0; i < 4; i++) {
        int row = warp_m * 64 + i * 16 + (lane & 15);
        aBase[i] = sb + (uint32_t)(row * ROW_BYTES);
        aSw[i] = (uint32_t)(row & 7);
    }
    uint32_t bBase[4]; uint32_t bSw[4];
    const int bK = (lane >> 3) & 1;
    const int nLoc = ((lane >> 4) << 3) + (lane & 7);
#pragma unroll
    for (int j2 = 0; j2 < 4; j2++) {
        int row = warp_n * 64 + j2 * 16 + nLoc;
        bBase[j2] = (uint32_t)(row * ROW_BYTES);
        bSw[j2] = (uint32_t)(row & 7);
    }

    int4 acc[4][8];
    float rs[8];
#pragma unroll
    for (int q = 0; q < 8; q++) rs[q] = 0.f;

    for (int t = 0; t < NTILES; t++) {
        const uint32_t bBuf = sb + A_BYTES + (uint32_t)((t & 1) * B_BYTES);

        // prefetch next B tile into the other buffer
        if (t + 1 < NTILES) {
            const int nb = t + 1;
            const uint32_t nBuf = sb + A_BYTES + (uint32_t)((nb & 1) * B_BYTES);
#pragma unroll
            for (int p = 0; p < 8; p++) {
                int idx = p * GTHREADS + tid;
                int r = idx >> 3, c = idx & 7;
                cp16(nBuf + (uint32_t)(r * ROW_BYTES + ((c ^ (r & 7)) << 4)),
                     &B4[(colBase + nb * TN + r) * 8 + c]);
            }
            CP_COMMIT();
        }

#pragma unroll
        for (int i = 0; i < 4; i++)
#pragma unroll
            for (int j = 0; j < 8; j++) acc[i][j] = make_int4(0, 0, 0, 0);

        // ---- k-loop: 4 steps of k=32 ----
#pragma unroll
        for (int ks = 0; ks < 4; ks++) {
            uint32_t a[4][4], bq[4][4];
#pragma unroll
            for (int i = 0; i < 4; i++) {
                uint32_t addr = aBase[i] + ((((uint32_t)(2 * ks + aK)) ^ aSw[i]) << 4);
                LDMX4(a[i][0], a[i][1], a[i][2], a[i][3], addr);
            }
#pragma unroll
            for (int j2 = 0; j2 < 4; j2++) {
                uint32_t addr = bBuf + bBase[j2] + ((((uint32_t)(2 * ks + bK)) ^ bSw[j2]) << 4);
                LDMX4(bq[j2][0], bq[j2][1], bq[j2][2], bq[j2][3], addr);
            }
#pragma unroll
            for (int i = 0; i < 4; i++)
#pragma unroll
                for (int j = 0; j < 8; j++)
                    mma_s8(acc[i][j], a[i][0], a[i][1], a[i][2], a[i][3],
                           bq[j >> 1][(j & 1) * 2], bq[j >> 1][(j & 1) * 2 + 1]);
        }

        // ---- epilogue: int acc -> clamp -> exp, from registers ----
        const bool isDiag = (t == tdiag);
#pragma unroll
        for (int i = 0; i < 4; i++) {
            const int r0 = warp_m * 64 + i * 16 + gid;
#pragma unroll
            for (int j = 0; j < 8; j++) {
                const int c0 = warp_n * 64 + j * 8 + tid4 * 2;
                int4 v = acc[i][j];
                float e0 = fmaxf((float)v.x, FCLAMP);
                float e1 = fmaxf((float)v.y, FCLAMP);
                float e2 = fmaxf((float)v.z, FCLAMP);
                float e3 = fmaxf((float)v.w, FCLAMP);
                rs[i * 2 + 0] += ex2f(fmaf(e0, wl, bl)) + ex2f(fmaf(e1, wl, bl));
                rs[i * 2 + 1] += ex2f(fmaf(e2, wl, bl)) + ex2f(fmaf(e3, wl, bl));
                if (isDiag) {
                    const int c = c0 - dOff;
                    if (r0 == c)         g_diag[rowBase + r0] = fmaf(e0, dm, b);
                    if (r0 == c + 1)     g_diag[rowBase + r0] = fmaf(e1, dm, b);
                    if (r0 + 8 == c)     g_diag[rowBase + r0 + 8] = fmaf(e2, dm, b);
                    if (r0 + 8 == c + 1) g_diag[rowBase + r0 + 8] = fmaf(e3, dm, b);
                }
            }
        }

        if (t + 1 < NTILES) CP_WAIT0();
        __syncthreads();
    }

    // ---- reduce rs across tid4 lanes (same rows), then across the 4 N-warps ----
#pragma unroll
    for (int q = 0; q < 8; q++) {
        rs[q] += __shfl_xor_sync(0xffffffffu, rs[q], 1);
        rs[q] += __shfl_xor_sync(0xffffffffu, rs[q], 2);
    }
    float* red = (float*)smem;   // 4 x 128 floats, reuse operand smem
    if (tid4 == 0) {
#pragma unroll
        for (int i = 0; i < 4; i++) {
            int r = warp_m * 64 + i * 16 + gid;
            red[warp_n * 128 + r] = rs[i * 2 + 0];
            red[warp_n * 128 + r + 8] = rs[i * 2 + 1];
        }
    }
    __syncthreads();
    if (tid < 128) {
        g_part[h][rowBase + tid] =
            red[tid] + red[128 + tid] + red[256 + tid] + red[384 + tid];
    }
}

// ---------------------------------------------------------------------------
// Kernel 3: loss = mean(log(rowsum) - diag_logit)
// ---------------------------------------------------------------------------
__global__ void __launch_bounds__(1024) final_kernel(float* __restrict__ out) {
    const int tid = threadIdx.x;
    const float LN2 = 0.69314718056f;
    float s = 0.f;
#pragma unroll
    for (int i = 0; i < 8; i++) {
        int r = tid + i * 1024;
        float sum = g_part[0][r] + g_part[1][r];
        s += lg2f(sum) * LN2 - g_diag[r];
    }
#pragma unroll
    for (int o = 16; o; o >>= 1) s += __shfl_xor_sync(0xffffffffu, s, o);
    __shared__ float sred[32];
    const int wid = tid >> 5, lane = tid & 31;
    if (lane == 0) sred[wid] = s;
    __syncthreads();
    if (wid == 0) {
        float v = sred[lane];
#pragma unroll
        for (int o = 16; o; o >>= 1) v += __shfl_xor_sync(0xffffffffu, v, o);
        if (lane == 0) out[0] = v * (1.0f / (float)N_SPK);
    }
}

extern "C" void kernel_launch(void* const* d_in, const int* in_sizes, int n_in,
                              void* d_out, int out_size) {
    const float* x = (const float*)d_in[0];
    const float* w = (const float*)d_in[1];
    const float* b = (const float*)d_in[2];
    float* out = (float*)d_out;
    (void)in_sizes; (void)n_in; (void)out_size;

    cudaFuncSetAttribute(gemm_lse_kernel,
                         cudaFuncAttributeMaxDynamicSharedMemorySize, SMEM_TOTAL);

    prep_kernel<<<N_SPK / 8, 256>>>(x);
    gemm_lse_kernel<<<dim3(2, 64), GTHREADS, SMEM_TOTAL>>>(w, b);
    final_kernel<<<1, 1024>>>(out);
}

// round 12
// speedup vs baseline: 2.3504x; 2.3504x over previous
#include <cuda_runtime.h>
#include <cuda_bf16.h>
#include <cstdint>

// ---------------- problem constants ----------------
#define N_SPK 8192
#define M_UTT 10
#define D_EMB 128
#define CLAMP_MIN 1e-6f

// ---------------- gemm tiling ----------------
#define TM 128                        // rows per CTA
#define TN 256                        // cols per tile
#define COLS_PER_CTA 4096             // grid.x = 2 column halves
#define NTILES (COLS_PER_CTA / TN)    // 16
#define GTHREADS 512                  // 16 warps: 4(M) x 4(N), warp tile 32x64

#define ROW_BYTES 256                 // 128 bf16
#define A_BYTES   (128 * ROW_BYTES)   // 32 KB
#define B_BYTES   (256 * ROW_BYTES)   // 64 KB per buffer
#define SMEM_TOTAL (A_BYTES + 2 * B_BYTES)   // 160 KB

// ---------------- device scratch ----------------
__device__ __align__(16) __nv_bfloat16 g_lhat[N_SPK * D_EMB];
__device__ __align__(16) __nv_bfloat16 g_chat[N_SPK * D_EMB];
__device__ float g_part[2][N_SPK];
__device__ float g_diag[N_SPK];

// ---------------- helpers ----------------
__device__ __forceinline__ uint32_t smem_u32(const void* p) {
    uint32_t a;
    asm("{ .reg .u64 t; cvta.to.shared.u64 t, %1; cvt.u32.u64 %0, t; }" : "=r"(a) : "l"(p));
    return a;
}
__device__ __forceinline__ void cp16(uint32_t dst, const void* src) {
    asm volatile("cp.async.cg.shared.global [%0], [%1], 16;" :: "r"(dst), "l"(src) : "memory");
}
#define CP_COMMIT() asm volatile("cp.async.commit_group;" ::: "memory")
#define CP_WAIT0()  asm volatile("cp.async.wait_group 0;" ::: "memory")

#define LDMX4(r0, r1, r2, r3, addr)                                            \
    asm volatile("ldmatrix.sync.aligned.m8n8.x4.shared.b16 {%0,%1,%2,%3}, [%4];" \
                 : "=r"(r0), "=r"(r1), "=r"(r2), "=r"(r3) : "r"(addr))

__device__ __forceinline__ void mma_bf16(float4& c, uint32_t a0, uint32_t a1,
                                         uint32_t a2, uint32_t a3,
                                         uint32_t b0, uint32_t b1) {
    asm volatile(
        "mma.sync.aligned.m16n8k16.row.col.f32.bf16.bf16.f32 "
        "{%0,%1,%2,%3}, {%4,%5,%6,%7}, {%8,%9}, {%0,%1,%2,%3};"
        : "+f"(c.x), "+f"(c.y), "+f"(c.z), "+f"(c.w)
        : "r"(a0), "r"(a1), "r"(a2), "r"(a3), "r"(b0), "r"(b1));
}

__device__ __forceinline__ float ex2f(float x) {
    float r; asm("ex2.approx.ftz.f32 %0, %1;" : "=f"(r) : "f"(x)); return r;
}
__device__ __forceinline__ float lg2f(float x) {
    float r; asm("lg2.approx.f32 %0, %1;" : "=f"(r) : "f"(x)); return r;
}

// ---------------------------------------------------------------------------
// Kernel 1: centroids + normalization + bf16 rounding. (DRAM-bound, ~10.5us)
// ---------------------------------------------------------------------------
__global__ void __launch_bounds__(256) prep_kernel(const float* __restrict__ x) {
    const int lane = threadIdx.x & 31;
    const int n = blockIdx.x * 8 + (threadIdx.x >> 5);
    const float4* xs = (const float4*)(x + (size_t)n * (M_UTT * D_EMB));

    float4 c = make_float4(0.f, 0.f, 0.f, 0.f);
    float4 l;
#pragma unroll
    for (int m = 0; m < M_UTT; m++) {
        float4 v = xs[m * 32 + lane];
        c.x += v.x; c.y += v.y; c.z += v.z; c.w += v.w;
        if (m == M_UTT - 1) l = v;
    }
    c.x *= 0.1f; c.y *= 0.1f; c.z *= 0.1f; c.w *= 0.1f;

    float sc = c.x * c.x + c.y * c.y + c.z * c.z + c.w * c.w;
    float sl = l.x * l.x + l.y * l.y + l.z * l.z + l.w * l.w;
#pragma unroll
    for (int o = 16; o; o >>= 1) {
        sc += __shfl_xor_sync(0xffffffffu, sc, o);
        sl += __shfl_xor_sync(0xffffffffu, sl, o);
    }
    const float rc = rsqrtf(sc), rl = rsqrtf(sl);

    __nv_bfloat162 c01 = __floats2bfloat162_rn(c.x * rc, c.y * rc);
    __nv_bfloat162 c23 = __floats2bfloat162_rn(c.z * rc, c.w * rc);
    __nv_bfloat162 l01 = __floats2bfloat162_rn(l.x * rl, l.y * rl);
    __nv_bfloat162 l23 = __floats2bfloat162_rn(l.z * rl, l.w * rl);

    uint2 cv, lv;
    cv.x = *(uint32_t*)&c01; cv.y = *(uint32_t*)&c23;
    lv.x = *(uint32_t*)&l01; lv.y = *(uint32_t*)&l23;
    ((uint2*)(g_chat + n * D_EMB))[lane] = cv;
    ((uint2*)(g_lhat + n * D_EMB))[lane] = lv;
}

// ---------------------------------------------------------------------------
// Kernel 2: mma.sync bf16 GEMM, 16 warps (4M x 4N), warp tile 32x64.
// Grid (2, 64), 512 threads. Smem: A 32KB + B double buffer 2x64KB = 160KB.
// 4 warps/SMSP so epilogue MUFU of some warps overlaps HMMA of others.
// Swizzle: 16B chunk c of row r stored at c ^ (r & 7).
// ---------------------------------------------------------------------------
__global__ void __launch_bounds__(GTHREADS, 1) gemm_lse_kernel(
    const float* __restrict__ wp, const float* __restrict__ bp) {
    extern __shared__ char smem[];
    const uint32_t sb = smem_u32(smem);

    const int tid = threadIdx.x;
    const int wid = tid >> 5, lane = tid & 31;
    const int warp_m = wid >> 2;          // 0..3 : 32-row stripe
    const int warp_n = wid & 3;           // 0..3 : 64-col stripe
    const int gid = lane >> 2;            // 0..7
    const int tid4 = lane & 3;

    const int h = blockIdx.x;
    const int rb = blockIdx.y;
    const int rowBase = rb * TM;
    const int colBase = h * COLS_PER_CTA;
    const int tdiag = ((rb >> 5) == h) ? ((rb - h * 32) >> 1) : -1;
    const int dOff = (rb & 1) * 128;      // local col offset of diag block

    const float w = *wp, b = *bp;
    const float LOG2E = 1.44269504f;
    const float wl = w * LOG2E, bl = b * LOG2E;

    // ---- async-load A stripe (4 chunks/thr) + B tile 0 (8 chunks/thr) ----
    const float4* A4 = (const float4*)g_lhat;
    const float4* B4 = (const float4*)g_chat;
#pragma unroll
    for (int p = 0; p < 4; p++) {
        int idx = p * GTHREADS + tid;
        int r = idx >> 4, c = idx & 15;
        cp16(sb + (uint32_t)(r * ROW_BYTES + ((c ^ (r & 7)) << 4)),
             &A4[(rowBase + r) * 16 + c]);
    }
#pragma unroll
    for (int p = 0; p < 8; p++) {
        int idx = p * GTHREADS + tid;
        int r = idx >> 4, c = idx & 15;
        cp16(sb + A_BYTES + (uint32_t)(r * ROW_BYTES + ((c ^ (r & 7)) << 4)),
             &B4[(colBase + r) * 16 + c]);
    }
    CP_COMMIT();
    CP_WAIT0();
    __syncthreads();

    // ---- ldmatrix lane-address precompute ----
    uint32_t aBase[2]; uint32_t aSw[2];
    const int aK = lane >> 4;
#pragma unroll
    for (int i = 0; i < 2; i++) {
        int row = warp_m * 32 + i * 16 + (lane & 15);
        aBase[i] = sb + (uint32_t)(row * ROW_BYTES);
        aSw[i] = (uint32_t)(row & 7);
    }
    uint32_t bBase[4]; uint32_t bSw[4];
    const int bK = (lane >> 3) & 1;
    const int nLoc = ((lane >> 4) << 3) + (lane & 7);
#pragma unroll
    for (int j2 = 0; j2 < 4; j2++) {
        int row = warp_n * 64 + j2 * 16 + nLoc;
        bBase[j2] = (uint32_t)(row * ROW_BYTES);
        bSw[j2] = (uint32_t)(row & 7);
    }

    float4 acc[2][8];
    float rs[4] = {0.f, 0.f, 0.f, 0.f};

    for (int t = 0; t < NTILES; t++) {
        const uint32_t bBuf = sb + A_BYTES + (uint32_t)((t & 1) * B_BYTES);

        // prefetch next B tile into the other buffer
        if (t + 1 < NTILES) {
            const int nb = t + 1;
            const uint32_t nBuf = sb + A_BYTES + (uint32_t)((nb & 1) * B_BYTES);
#pragma unroll
            for (int p = 0; p < 8; p++) {
                int idx = p * GTHREADS + tid;
                int r = idx >> 4, c = idx & 15;
                cp16(nBuf + (uint32_t)(r * ROW_BYTES + ((c ^ (r & 7)) << 4)),
                     &B4[(colBase + nb * TN + r) * 16 + c]);
            }
            CP_COMMIT();
        }

#pragma unroll
        for (int i = 0; i < 2; i++)
#pragma unroll
            for (int j = 0; j < 8; j++) acc[i][j] = make_float4(0.f, 0.f, 0.f, 0.f);

        // ---- k-loop: 8 steps of k=16 ----
#pragma unroll
        for (int ks = 0; ks < 8; ks++) {
            uint32_t a[2][4], bq[4][4];
#pragma unroll
            for (int i = 0; i < 2; i++) {
                uint32_t addr = aBase[i] + ((((uint32_t)(2 * ks + aK)) ^ aSw[i]) << 4);
                LDMX4(a[i][0], a[i][1], a[i][2], a[i][3], addr);
            }
#pragma unroll
            for (int j2 = 0; j2 < 4; j2++) {
                uint32_t addr = bBuf + bBase[j2] + ((((uint32_t)(2 * ks + bK)) ^ bSw[j2]) << 4);
                LDMX4(bq[j2][0], bq[j2][1], bq[j2][2], bq[j2][3], addr);
            }
#pragma unroll
            for (int i = 0; i < 2; i++)
#pragma unroll
                for (int j = 0; j < 8; j++)
                    mma_bf16(acc[i][j], a[i][0], a[i][1], a[i][2], a[i][3],
                             bq[j >> 1][(j & 1) * 2], bq[j >> 1][(j & 1) * 2 + 1]);
        }

        // ---- epilogue: exp from registers ----
        const bool isDiag = (t == tdiag);
#pragma unroll
        for (int i = 0; i < 2; i++) {
            const int r0 = warp_m * 32 + i * 16 + gid;
#pragma unroll
            for (int j = 0; j < 8; j++) {
                const int c0 = warp_n * 64 + j * 8 + tid4 * 2;
                float4 v = acc[i][j];
                float e0 = fmaxf(v.x, CLAMP_MIN);
                float e1 = fmaxf(v.y, CLAMP_MIN);
                float e2 = fmaxf(v.z, CLAMP_MIN);
                float e3 = fmaxf(v.w, CLAMP_MIN);
                rs[i * 2 + 0] += ex2f(fmaf(e0, wl, bl)) + ex2f(fmaf(e1, wl, bl));
                rs[i * 2 + 1] += ex2f(fmaf(e2, wl, bl)) + ex2f(fmaf(e3, wl, bl));
                if (isDiag) {
                    const int c = c0 - dOff;
                    if (r0 == c)         g_diag[rowBase + r0] = fmaf(e0, w, b);
                    if (r0 == c + 1)     g_diag[rowBase + r0] = fmaf(e1, w, b);
                    if (r0 + 8 == c)     g_diag[rowBase + r0 + 8] = fmaf(e2, w, b);
                    if (r0 + 8 == c + 1) g_diag[rowBase + r0 + 8] = fmaf(e3, w, b);
                }
            }
        }

        if (t + 1 < NTILES) CP_WAIT0();
        __syncthreads();
    }

    // ---- reduce rs across tid4 lanes (same rows), then across the 4 N-warps ----
#pragma unroll
    for (int q = 0; q < 4; q++) {
        rs[q] += __shfl_xor_sync(0xffffffffu, rs[q], 1);
        rs[q] += __shfl_xor_sync(0xffffffffu, rs[q], 2);
    }
    float* red = (float*)smem;   // 4 x 128 floats, reuse operand smem
    if (tid4 == 0) {
#pragma unroll
        for (int i = 0; i < 2; i++) {
            int r = warp_m * 32 + i * 16 + gid;
            red[warp_n * 128 + r] = rs[i * 2 + 0];
            red[warp_n * 128 + r + 8] = rs[i * 2 + 1];
        }
    }
    __syncthreads();
    if (tid < 128) {
        g_part[h][rowBase + tid] =
            red[tid] + red[128 + tid] + red[256 + tid] + red[384 + tid];
    }
}

// ---------------------------------------------------------------------------
// Kernel 3: loss = mean(log(rowsum) - diag_logit)
// ---------------------------------------------------------------------------
__global__ void __launch_bounds__(1024) final_kernel(float* __restrict__ out) {
    const int tid = threadIdx.x;
    const float LN2 = 0.69314718056f;
    float s = 0.f;
#pragma unroll
    for (int i = 0; i < 8; i++) {
        int r = tid + i * 1024;
        float sum = g_part[0][r] + g_part[1][r];
        s += lg2f(sum) * LN2 - g_diag[r];
    }
#pragma unroll
    for (int o = 16; o; o >>= 1) s += __shfl_xor_sync(0xffffffffu, s, o);
    __shared__ float sred[32];
    const int wid = tid >> 5, lane = tid & 31;
    if (lane == 0) sred[wid] = s;
    __syncthreads();
    if (wid == 0) {
        float v = sred[lane];
#pragma unroll
        for (int o = 16; o; o >>= 1) v += __shfl_xor_sync(0xffffffffu, v, o);
        if (lane == 0) out[0] = v * (1.0f / (float)N_SPK);
    }
}

extern "C" void kernel_launch(void* const* d_in, const int* in_sizes, int n_in,
                              void* d_out, int out_size) {
    const float* x = (const float*)d_in[0];
    const float* w = (const float*)d_in[1];
    const float* b = (const float*)d_in[2];
    float* out = (float*)d_out;
    (void)in_sizes; (void)n_in; (void)out_size;

    cudaFuncSetAttribute(gemm_lse_kernel,
                         cudaFuncAttributeMaxDynamicSharedMemorySize, SMEM_TOTAL);

    prep_kernel<<<N_SPK / 8, 256>>>(x);
    gemm_lse_kernel<<<dim3(2, 64), GTHREADS, SMEM_TOTAL>>>(w, b);
    final_kernel<<<1, 1024>>>(out);
}

// round 13
// speedup vs baseline: 2.5005x; 1.0639x over previous
#include <cuda_runtime.h>
#include <cuda_bf16.h>
#include <cstdint>

// ---------------- problem constants ----------------
#define N_SPK 8192
#define M_UTT 10
#define D_EMB 128
#define CLAMP_MIN 1e-6f

// ---------------- gemm tiling ----------------
#define TM 128
#define TN 256
#define NCT 32                         // col tiles per row block
#define NRB 64                         // row blocks
#define TOTAL_TILES (NRB * NCT)        // 2048
#define NCTA 148                       // one CTA per SM, one wave
#define GTHREADS 256                   // 8 warps: 2(M) x 4(N), warp tile 64x64

#define ROW_BYTES 256                  // 128 bf16
#define A_BYTES (128 * ROW_BYTES)      // 32 KB
#define B_BYTES (256 * ROW_BYTES)      // 64 KB
#define OFF_B0  (2 * A_BYTES)          // A double buffer at 0 / 32KB
#define OFF_RED (2 * A_BYTES + 2 * B_BYTES)
#define SMEM_TOTAL (OFF_RED + 2048)    // 194 KB + 2KB reduction pad

// ---------------- device scratch ----------------
__device__ __align__(16) __nv_bfloat16 g_lhat[N_SPK * D_EMB];
__device__ __align__(16) __nv_bfloat16 g_chat[N_SPK * D_EMB];
__device__ float g_partF[NCT][N_SPK];  // per (col-tile, row) exp-sum partial
__device__ float g_rows[N_SPK];        // per-row  log(sum) - diag
__device__ float g_diag[N_SPK];

// ---------------- helpers ----------------
__device__ __forceinline__ uint32_t smem_u32(const void* p) {
    uint32_t a;
    asm("{ .reg .u64 t; cvta.to.shared.u64 t, %1; cvt.u32.u64 %0, t; }" : "=r"(a) : "l"(p));
    return a;
}
__device__ __forceinline__ void cp16(uint32_t dst, const void* src) {
    asm volatile("cp.async.cg.shared.global [%0], [%1], 16;" :: "r"(dst), "l"(src) : "memory");
}
#define CP_COMMIT() asm volatile("cp.async.commit_group;" ::: "memory")
#define CP_WAIT0()  asm volatile("cp.async.wait_group 0;" ::: "memory")

#define LDMX4(r0, r1, r2, r3, addr)                                            \
    asm volatile("ldmatrix.sync.aligned.m8n8.x4.shared.b16 {%0,%1,%2,%3}, [%4];" \
                 : "=r"(r0), "=r"(r1), "=r"(r2), "=r"(r3) : "r"(addr))

__device__ __forceinline__ void mma_bf16(float4& c, uint32_t a0, uint32_t a1,
                                         uint32_t a2, uint32_t a3,
                                         uint32_t b0, uint32_t b1) {
    asm volatile(
        "mma.sync.aligned.m16n8k16.row.col.f32.bf16.bf16.f32 "
        "{%0,%1,%2,%3}, {%4,%5,%6,%7}, {%8,%9}, {%0,%1,%2,%3};"
        : "+f"(c.x), "+f"(c.y), "+f"(c.z), "+f"(c.w)
        : "r"(a0), "r"(a1), "r"(a2), "r"(a3), "r"(b0), "r"(b1));
}

__device__ __forceinline__ float ex2f(float x) {
    float r; asm("ex2.approx.ftz.f32 %0, %1;" : "=f"(r) : "f"(x)); return r;
}
__device__ __forceinline__ float lg2f(float x) {
    float r; asm("lg2.approx.f32 %0, %1;" : "=f"(r) : "f"(x)); return r;
}

// ---------------------------------------------------------------------------
// Kernel 1: centroids + normalization + bf16 rounding. (DRAM-bound, ~10.5us)
// ---------------------------------------------------------------------------
__global__ void __launch_bounds__(256) prep_kernel(const float* __restrict__ x) {
    const int lane = threadIdx.x & 31;
    const int n = blockIdx.x * 8 + (threadIdx.x >> 5);
    const float4* xs = (const float4*)(x + (size_t)n * (M_UTT * D_EMB));

    float4 c = make_float4(0.f, 0.f, 0.f, 0.f);
    float4 l;
#pragma unroll
    for (int m = 0; m < M_UTT; m++) {
        float4 v = xs[m * 32 + lane];
        c.x += v.x; c.y += v.y; c.z += v.z; c.w += v.w;
        if (m == M_UTT - 1) l = v;
    }
    c.x *= 0.1f; c.y *= 0.1f; c.z *= 0.1f; c.w *= 0.1f;

    float sc = c.x * c.x + c.y * c.y + c.z * c.z + c.w * c.w;
    float sl = l.x * l.x + l.y * l.y + l.z * l.z + l.w * l.w;
#pragma unroll
    for (int o = 16; o; o >>= 1) {
        sc += __shfl_xor_sync(0xffffffffu, sc, o);
        sl += __shfl_xor_sync(0xffffffffu, sl, o);
    }
    const float rc = rsqrtf(sc), rl = rsqrtf(sl);

    __nv_bfloat162 c01 = __floats2bfloat162_rn(c.x * rc, c.y * rc);
    __nv_bfloat162 c23 = __floats2bfloat162_rn(c.z * rc, c.w * rc);
    __nv_bfloat162 l01 = __floats2bfloat162_rn(l.x * rl, l.y * rl);
    __nv_bfloat162 l23 = __floats2bfloat162_rn(l.z * rl, l.w * rl);

    uint2 cv, lv;
    cv.x = *(uint32_t*)&c01; cv.y = *(uint32_t*)&c23;
    lv.x = *(uint32_t*)&l01; lv.y = *(uint32_t*)&l23;
    ((uint2*)(g_chat + n * D_EMB))[lane] = cv;
    ((uint2*)(g_lhat + n * D_EMB))[lane] = lv;
}

// ---------------------------------------------------------------------------
// Kernel 2: persistent bf16 mma.sync GEMM over 148 CTAs.
// Work = 2048 tiles (64 row-blocks x 32 col-tiles of 128x256). CTA k owns the
// contiguous tile range [k*2048/148, (k+1)*2048/148). Per-tile row partials go
// to g_partF[ct][row] (each slot written by exactly one CTA -> deterministic).
// Smem: A double buffer 2x32KB + B double buffer 2x64KB + 2KB reduce = 194KB.
// ---------------------------------------------------------------------------
__global__ void __launch_bounds__(GTHREADS, 1) gemm_lse_kernel(
    const float* __restrict__ wp, const float* __restrict__ bp) {
    extern __shared__ char smem[];
    const uint32_t sb = smem_u32(smem);

    const int tid = threadIdx.x;
    const int wid = tid >> 5, lane = tid & 31;
    const int warp_m = wid >> 2;          // 0..1 : 64-row stripe
    const int warp_n = wid & 3;           // 0..3 : 64-col stripe
    const int gid = lane >> 2;            // 0..7
    const int tid4 = lane & 3;

    const int bid = blockIdx.x;
    const int lo = (bid * TOTAL_TILES) / NCTA;
    const int hi = ((bid + 1) * TOTAL_TILES) / NCTA;

    const float w = *wp, b = *bp;
    const float LOG2E = 1.44269504f;
    const float wl = w * LOG2E, bl = b * LOG2E;

    const float4* A4 = (const float4*)g_lhat;
    const float4* B4 = (const float4*)g_chat;

    // ---- initial loads: A(rb of first tile) -> buf0, B(first tile) -> buf0 ----
    int rb = lo >> 5;
    {
        const int ct = lo & 31;
#pragma unroll
        for (int p = 0; p < 8; p++) {
            int idx = p * GTHREADS + tid;
            int r = idx >> 4, c = idx & 15;
            cp16(sb + (uint32_t)(r * ROW_BYTES + ((c ^ (r & 7)) << 4)),
                 &A4[(rb * TM + r) * 16 + c]);
        }
#pragma unroll
        for (int p = 0; p < 16; p++) {
            int idx = p * GTHREADS + tid;
            int r = idx >> 4, c = idx & 15;
            cp16(sb + OFF_B0 + (uint32_t)(r * ROW_BYTES + ((c ^ (r & 7)) << 4)),
                 &B4[(ct * TN + r) * 16 + c]);
        }
        CP_COMMIT();
        CP_WAIT0();
        __syncthreads();
    }

    // ---- ldmatrix lane-relative offsets ----
    uint32_t aOff[4], aSw[4];
    const int aK = lane >> 4;
#pragma unroll
    for (int i = 0; i < 4; i++) {
        int row = warp_m * 64 + i * 16 + (lane & 15);
        aOff[i] = (uint32_t)(row * ROW_BYTES);
        aSw[i] = (uint32_t)(row & 7);
    }
    uint32_t bOff[4], bSw[4];
    const int bK = (lane >> 3) & 1;
    const int nLoc = ((lane >> 4) << 3) + (lane & 7);
#pragma unroll
    for (int j2 = 0; j2 < 4; j2++) {
        int row = warp_n * 64 + j2 * 16 + nLoc;
        bOff[j2] = (uint32_t)(row * ROW_BYTES);
        bSw[j2] = (uint32_t)(row & 7);
    }

    float4 acc[4][8];
    float* red = (float*)(smem + OFF_RED);
    int aCur = 0;

    for (int t = lo; t < hi; t++) {
        const int bCur = (t - lo) & 1;
        const int ct = t & 31;
        const int rowBase = rb * TM;
        const uint32_t aBuf = sb + (uint32_t)(aCur * A_BYTES);
        const uint32_t bBuf = sb + OFF_B0 + (uint32_t)(bCur * B_BYTES);

        // ---- prefetch next tile (B always; A only on row-block change) ----
        bool aSwap = false;
        if (t + 1 < hi) {
            const int rbn = (t + 1) >> 5, ctn = (t + 1) & 31;
            aSwap = (rbn != rb);
            if (aSwap) {
                const uint32_t nA = sb + (uint32_t)((aCur ^ 1) * A_BYTES);
#pragma unroll
                for (int p = 0; p < 8; p++) {
                    int idx = p * GTHREADS + tid;
                    int r = idx >> 4, c = idx & 15;
                    cp16(nA + (uint32_t)(r * ROW_BYTES + ((c ^ (r & 7)) << 4)),
                         &A4[(rbn * TM + r) * 16 + c]);
                }
            }
            const uint32_t nB = sb + OFF_B0 + (uint32_t)((bCur ^ 1) * B_BYTES);
#pragma unroll
            for (int p = 0; p < 16; p++) {
                int idx = p * GTHREADS + tid;
                int r = idx >> 4, c = idx & 15;
                cp16(nB + (uint32_t)(r * ROW_BYTES + ((c ^ (r & 7)) << 4)),
                     &B4[(ctn * TN + r) * 16 + c]);
            }
            CP_COMMIT();
        }

#pragma unroll
        for (int i = 0; i < 4; i++)
#pragma unroll
            for (int j = 0; j < 8; j++) acc[i][j] = make_float4(0.f, 0.f, 0.f, 0.f);

        // ---- k-loop: 8 steps of k=16 ----
#pragma unroll
        for (int ks = 0; ks < 8; ks++) {
            uint32_t a[4][4], bq[4][4];
#pragma unroll
            for (int i = 0; i < 4; i++) {
                uint32_t addr = aBuf + aOff[i] + ((((uint32_t)(2 * ks + aK)) ^ aSw[i]) << 4);
                LDMX4(a[i][0], a[i][1], a[i][2], a[i][3], addr);
            }
#pragma unroll
            for (int j2 = 0; j2 < 4; j2++) {
                uint32_t addr = bBuf + bOff[j2] + ((((uint32_t)(2 * ks + bK)) ^ bSw[j2]) << 4);
                LDMX4(bq[j2][0], bq[j2][1], bq[j2][2], bq[j2][3], addr);
            }
#pragma unroll
            for (int i = 0; i < 4; i++)
#pragma unroll
                for (int j = 0; j < 8; j++)
                    mma_bf16(acc[i][j], a[i][0], a[i][1], a[i][2], a[i][3],
                             bq[j >> 1][(j & 1) * 2], bq[j >> 1][(j & 1) * 2 + 1]);
        }

        // ---- epilogue: exp from registers into per-tile row sums ----
        float rs[8];
#pragma unroll
        for (int q = 0; q < 8; q++) rs[q] = 0.f;
        const bool isDiag = (ct == (rb >> 1));
        const int dOff = (rb & 1) * 128;
#pragma unroll
        for (int i = 0; i < 4; i++) {
            const int r0 = warp_m * 64 + i * 16 + gid;
#pragma unroll
            for (int j = 0; j < 8; j++) {
                const int c0 = warp_n * 64 + j * 8 + tid4 * 2;
                float4 v = acc[i][j];
                float e0 = fmaxf(v.x, CLAMP_MIN);
                float e1 = fmaxf(v.y, CLAMP_MIN);
                float e2 = fmaxf(v.z, CLAMP_MIN);
                float e3 = fmaxf(v.w, CLAMP_MIN);
                rs[i * 2 + 0] += ex2f(fmaf(e0, wl, bl)) + ex2f(fmaf(e1, wl, bl));
                rs[i * 2 + 1] += ex2f(fmaf(e2, wl, bl)) + ex2f(fmaf(e3, wl, bl));
                if (isDiag) {
                    const int c = c0 - dOff;
                    if (r0 == c)         g_diag[rowBase + r0] = fmaf(e0, w, b);
                    if (r0 == c + 1)     g_diag[rowBase + r0] = fmaf(e1, w, b);
                    if (r0 + 8 == c)     g_diag[rowBase + r0 + 8] = fmaf(e2, w, b);
                    if (r0 + 8 == c + 1) g_diag[rowBase + r0 + 8] = fmaf(e3, w, b);
                }
            }
        }

        // ---- per-tile flush: reduce 128 row partials, store to g_partF ----
#pragma unroll
        for (int q = 0; q < 8; q++) {
            rs[q] += __shfl_xor_sync(0xffffffffu, rs[q], 1);
            rs[q] += __shfl_xor_sync(0xffffffffu, rs[q], 2);
        }
        if (tid4 == 0) {
#pragma unroll
            for (int i = 0; i < 4; i++) {
                int r = warp_m * 64 + i * 16 + gid;
                red[warp_n * 128 + r] = rs[i * 2 + 0];
                red[warp_n * 128 + r + 8] = rs[i * 2 + 1];
            }
        }
        __syncthreads();
        if (tid < 128)
            g_partF[ct][rowBase + tid] =
                red[tid] + red[128 + tid] + red[256 + tid] + red[384 + tid];

        if (t + 1 < hi) CP_WAIT0();
        __syncthreads();
        if (aSwap) { rb = (t + 1) >> 5; aCur ^= 1; }
    }
}

// ---------------------------------------------------------------------------
// Kernel 3a: per-row  log(sum of 32 partials) - diag_logit   (64 CTAs)
// ---------------------------------------------------------------------------
__global__ void __launch_bounds__(128) final1_kernel() {
    const int r = blockIdx.x * 128 + threadIdx.x;
    const float LN2 = 0.69314718056f;
    float sum = 0.f;
#pragma unroll
    for (int ct = 0; ct < NCT; ct++) sum += g_partF[ct][r];
    g_rows[r] = lg2f(sum) * LN2 - g_diag[r];
}

// ---------------------------------------------------------------------------
// Kernel 3b: loss = mean(g_rows)
// ---------------------------------------------------------------------------
__global__ void __launch_bounds__(1024) final2_kernel(float* __restrict__ out) {
    const int tid = threadIdx.x;
    float s = 0.f;
#pragma unroll
    for (int i = 0; i < 8; i++) s += g_rows[tid + i * 1024];
#pragma unroll
    for (int o = 16; o; o >>= 1) s += __shfl_xor_sync(0xffffffffu, s, o);
    __shared__ float sred[32];
    const int wid = tid >> 5, lane = tid & 31;
    if (lane == 0) sred[wid] = s;
    __syncthreads();
    if (wid == 0) {
        float v = sred[lane];
#pragma unroll
        for (int o = 16; o; o >>= 1) v += __shfl_xor_sync(0xffffffffu, v, o);
        if (lane == 0) out[0] = v * (1.0f / (float)N_SPK);
    }
}

extern "C" void kernel_launch(void* const* d_in, const int* in_sizes, int n_in,
                              void* d_out, int out_size) {
    const float* x = (const float*)d_in[0];
    const float* w = (const float*)d_in[1];
    const float* b = (const float*)d_in[2];
    float* out = (float*)d_out;
    (void)in_sizes; (void)n_in; (void)out_size;

    cudaFuncSetAttribute(gemm_lse_kernel,
                         cudaFuncAttributeMaxDynamicSharedMemorySize, SMEM_TOTAL);

    prep_kernel<<<N_SPK / 8, 256>>>(x);
    gemm_lse_kernel<<<NCTA, GTHREADS, SMEM_TOTAL>>>(w, b);
    final1_kernel<<<N_SPK / 128, 128>>>();
    final2_kernel<<<1, 1024>>>(out);
}

// round 14
// speedup vs baseline: 2.6360x; 1.0542x over previous
#include <cuda_runtime.h>
#include <cuda_bf16.h>
#include <cstdint>

// ---------------- problem constants ----------------
#define N_SPK 8192
#define M_UTT 10
#define D_EMB 128
#define CLAMP_MIN 1e-6f

// ---------------- gemm tiling ----------------
#define TM 128
#define TN 256
#define NCT 32                         // col tiles per row block
#define NRB 64                         // row blocks
#define TOTAL_TILES (NRB * NCT)        // 2048
#define NCTA 148                       // one CTA per SM, one wave
#define GTHREADS 256                   // 8 warps: 2(M) x 4(N), warp tile 64x64

#define ROW_BYTES 256                  // 128 bf16
#define A_BYTES (128 * ROW_BYTES)      // 32 KB
#define B_BYTES (256 * ROW_BYTES)      // 64 KB
#define OFF_B0  (2 * A_BYTES)          // A double buffer at 0 / 32KB
#define OFF_RED (2 * A_BYTES + 2 * B_BYTES)
#define SMEM_TOTAL (OFF_RED + 2048)    // 194 KB + 2KB reduction pad

// ---------------- device scratch ----------------
__device__ __align__(16) __nv_bfloat16 g_lhat[N_SPK * D_EMB];
__device__ __align__(16) __nv_bfloat16 g_chat[N_SPK * D_EMB];
// Sparse per-segment exp-sum partials: slot = ct of the CTA-segment's first
// tile. Unwritten slots are zero-initialized at module load and never touched
// (each written slot has exactly one writer per launch -> deterministic).
__device__ float g_partF[NCT][N_SPK];
__device__ float g_diag[N_SPK];
__device__ float g_blk[NRB];           // per-row-block partial loss sums

// ---------------- helpers ----------------
__device__ __forceinline__ uint32_t smem_u32(const void* p) {
    uint32_t a;
    asm("{ .reg .u64 t; cvta.to.shared.u64 t, %1; cvt.u32.u64 %0, t; }" : "=r"(a) : "l"(p));
    return a;
}
__device__ __forceinline__ void cp16(uint32_t dst, const void* src) {
    asm volatile("cp.async.cg.shared.global [%0], [%1], 16;" :: "r"(dst), "l"(src) : "memory");
}
#define CP_COMMIT() asm volatile("cp.async.commit_group;" ::: "memory")
#define CP_WAIT0()  asm volatile("cp.async.wait_group 0;" ::: "memory")

#define LDMX4(r0, r1, r2, r3, addr)                                            \
    asm volatile("ldmatrix.sync.aligned.m8n8.x4.shared.b16 {%0,%1,%2,%3}, [%4];" \
                 : "=r"(r0), "=r"(r1), "=r"(r2), "=r"(r3) : "r"(addr))

__device__ __forceinline__ void mma_bf16(float4& c, uint32_t a0, uint32_t a1,
                                         uint32_t a2, uint32_t a3,
                                         uint32_t b0, uint32_t b1) {
    asm volatile(
        "mma.sync.aligned.m16n8k16.row.col.f32.bf16.bf16.f32 "
        "{%0,%1,%2,%3}, {%4,%5,%6,%7}, {%8,%9}, {%0,%1,%2,%3};"
        : "+f"(c.x), "+f"(c.y), "+f"(c.z), "+f"(c.w)
        : "r"(a0), "r"(a1), "r"(a2), "r"(a3), "r"(b0), "r"(b1));
}

__device__ __forceinline__ float ex2f(float x) {
    float r; asm("ex2.approx.ftz.f32 %0, %1;" : "=f"(r) : "f"(x)); return r;
}
__device__ __forceinline__ float lg2f(float x) {
    float r; asm("lg2.approx.f32 %0, %1;" : "=f"(r) : "f"(x)); return r;
}

// ---------------------------------------------------------------------------
// Kernel 1: centroids + normalization + bf16 rounding. (DRAM-bound, ~10.5us)
// ---------------------------------------------------------------------------
__global__ void __launch_bounds__(256) prep_kernel(const float* __restrict__ x) {
    const int lane = threadIdx.x & 31;
    const int n = blockIdx.x * 8 + (threadIdx.x >> 5);
    const float4* xs = (const float4*)(x + (size_t)n * (M_UTT * D_EMB));

    float4 c = make_float4(0.f, 0.f, 0.f, 0.f);
    float4 l;
#pragma unroll
    for (int m = 0; m < M_UTT; m++) {
        float4 v = xs[m * 32 + lane];
        c.x += v.x; c.y += v.y; c.z += v.z; c.w += v.w;
        if (m == M_UTT - 1) l = v;
    }
    c.x *= 0.1f; c.y *= 0.1f; c.z *= 0.1f; c.w *= 0.1f;

    float sc = c.x * c.x + c.y * c.y + c.z * c.z + c.w * c.w;
    float sl = l.x * l.x + l.y * l.y + l.z * l.z + l.w * l.w;
#pragma unroll
    for (int o = 16; o; o >>= 1) {
        sc += __shfl_xor_sync(0xffffffffu, sc, o);
        sl += __shfl_xor_sync(0xffffffffu, sl, o);
    }
    const float rc = rsqrtf(sc), rl = rsqrtf(sl);

    __nv_bfloat162 c01 = __floats2bfloat162_rn(c.x * rc, c.y * rc);
    __nv_bfloat162 c23 = __floats2bfloat162_rn(c.z * rc, c.w * rc);
    __nv_bfloat162 l01 = __floats2bfloat162_rn(l.x * rl, l.y * rl);
    __nv_bfloat162 l23 = __floats2bfloat162_rn(l.z * rl, l.w * rl);

    uint2 cv, lv;
    cv.x = *(uint32_t*)&c01; cv.y = *(uint32_t*)&c23;
    lv.x = *(uint32_t*)&l01; lv.y = *(uint32_t*)&l23;
    ((uint2*)(g_chat + n * D_EMB))[lane] = cv;
    ((uint2*)(g_lhat + n * D_EMB))[lane] = lv;
}

// ---------------------------------------------------------------------------
// Kernel 2: persistent bf16 mma.sync GEMM over 148 CTAs.
// 2048 tiles (64 rb x 32 ct); CTA k owns [k*2048/148,(k+1)*2048/148).
// Row exp-sums accumulate in registers across each row-block segment and are
// flushed ONCE per segment (2-3x per CTA) to g_partF[segment-start-ct][row].
// ---------------------------------------------------------------------------
__global__ void __launch_bounds__(GTHREADS, 1) gemm_lse_kernel(
    const float* __restrict__ wp, const float* __restrict__ bp) {
    extern __shared__ char smem[];
    const uint32_t sb = smem_u32(smem);

    const int tid = threadIdx.x;
    const int wid = tid >> 5, lane = tid & 31;
    const int warp_m = wid >> 2;          // 0..1 : 64-row stripe
    const int warp_n = wid & 3;           // 0..3 : 64-col stripe
    const int gid = lane >> 2;            // 0..7
    const int tid4 = lane & 3;

    const int bid = blockIdx.x;
    const int lo = (bid * TOTAL_TILES) / NCTA;
    const int hi = ((bid + 1) * TOTAL_TILES) / NCTA;

    const float w = *wp, b = *bp;
    const float LOG2E = 1.44269504f;
    const float wl = w * LOG2E, bl = b * LOG2E;

    const float4* A4 = (const float4*)g_lhat;
    const float4* B4 = (const float4*)g_chat;

    // ---- initial loads ----
    int rb = lo >> 5;
    {
        const int ct = lo & 31;
#pragma unroll
        for (int p = 0; p < 8; p++) {
            int idx = p * GTHREADS + tid;
            int r = idx >> 4, c = idx & 15;
            cp16(sb + (uint32_t)(r * ROW_BYTES + ((c ^ (r & 7)) << 4)),
                 &A4[(rb * TM + r) * 16 + c]);
        }
#pragma unroll
        for (int p = 0; p < 16; p++) {
            int idx = p * GTHREADS + tid;
            int r = idx >> 4, c = idx & 15;
            cp16(sb + OFF_B0 + (uint32_t)(r * ROW_BYTES + ((c ^ (r & 7)) << 4)),
                 &B4[(ct * TN + r) * 16 + c]);
        }
        CP_COMMIT();
        CP_WAIT0();
        __syncthreads();
    }

    // ---- ldmatrix lane-relative offsets ----
    uint32_t aOff[4], aSw[4];
    const int aK = lane >> 4;
#pragma unroll
    for (int i = 0; i < 4; i++) {
        int row = warp_m * 64 + i * 16 + (lane & 15);
        aOff[i] = (uint32_t)(row * ROW_BYTES);
        aSw[i] = (uint32_t)(row & 7);
    }
    uint32_t bOff[4], bSw[4];
    const int bK = (lane >> 3) & 1;
    const int nLoc = ((lane >> 4) << 3) + (lane & 7);
#pragma unroll
    for (int j2 = 0; j2 < 4; j2++) {
        int row = warp_n * 64 + j2 * 16 + nLoc;
        bOff[j2] = (uint32_t)(row * ROW_BYTES);
        bSw[j2] = (uint32_t)(row & 7);
    }

    float4 acc[4][8];
    float rs[8];
#pragma unroll
    for (int q = 0; q < 8; q++) rs[q] = 0.f;
    float* red = (float*)(smem + OFF_RED);
    int aCur = 0;
    int segCt = lo & 31;                  // g_partF slot of current segment

    for (int t = lo; t < hi; t++) {
        const int bCur = (t - lo) & 1;
        const int ct = t & 31;
        const int rowBase = rb * TM;
        const uint32_t aBuf = sb + (uint32_t)(aCur * A_BYTES);
        const uint32_t bBuf = sb + OFF_B0 + (uint32_t)(bCur * B_BYTES);

        // ---- prefetch next tile (B always; A only on row-block change) ----
        bool aSwap = false;
        if (t + 1 < hi) {
            const int rbn = (t + 1) >> 5, ctn = (t + 1) & 31;
            aSwap = (rbn != rb);
            if (aSwap) {
                const uint32_t nA = sb + (uint32_t)((aCur ^ 1) * A_BYTES);
#pragma unroll
                for (int p = 0; p < 8; p++) {
                    int idx = p * GTHREADS + tid;
                    int r = idx >> 4, c = idx & 15;
                    cp16(nA + (uint32_t)(r * ROW_BYTES + ((c ^ (r & 7)) << 4)),
                         &A4[(rbn * TM + r) * 16 + c]);
                }
            }
            const uint32_t nB = sb + OFF_B0 + (uint32_t)((bCur ^ 1) * B_BYTES);
#pragma unroll
            for (int p = 0; p < 16; p++) {
                int idx = p * GTHREADS + tid;
                int r = idx >> 4, c = idx & 15;
                cp16(nB + (uint32_t)(r * ROW_BYTES + ((c ^ (r & 7)) << 4)),
                     &B4[(ctn * TN + r) * 16 + c]);
            }
            CP_COMMIT();
        }

#pragma unroll
        for (int i = 0; i < 4; i++)
#pragma unroll
            for (int j = 0; j < 8; j++) acc[i][j] = make_float4(0.f, 0.f, 0.f, 0.f);

        // ---- k-loop: 8 steps of k=16 ----
#pragma unroll
        for (int ks = 0; ks < 8; ks++) {
            uint32_t a[4][4], bq[4][4];
#pragma unroll
            for (int i = 0; i < 4; i++) {
                uint32_t addr = aBuf + aOff[i] + ((((uint32_t)(2 * ks + aK)) ^ aSw[i]) << 4);
                LDMX4(a[i][0], a[i][1], a[i][2], a[i][3], addr);
            }
#pragma unroll
            for (int j2 = 0; j2 < 4; j2++) {
                uint32_t addr = bBuf + bOff[j2] + ((((uint32_t)(2 * ks + bK)) ^ bSw[j2]) << 4);
                LDMX4(bq[j2][0], bq[j2][1], bq[j2][2], bq[j2][3], addr);
            }
#pragma unroll
            for (int i = 0; i < 4; i++)
#pragma unroll
                for (int j = 0; j < 8; j++)
                    mma_bf16(acc[i][j], a[i][0], a[i][1], a[i][2], a[i][3],
                             bq[j >> 1][(j & 1) * 2], bq[j >> 1][(j & 1) * 2 + 1]);
        }

        // ---- epilogue: exp from registers into segment-persistent rs ----
        const bool isDiag = (ct == (rb >> 1));
        const int dOff = (rb & 1) * 128;
#pragma unroll
        for (int i = 0; i < 4; i++) {
            const int r0 = warp_m * 64 + i * 16 + gid;
#pragma unroll
            for (int j = 0; j < 8; j++) {
                const int c0 = warp_n * 64 + j * 8 + tid4 * 2;
                float4 v = acc[i][j];
                float e0 = fmaxf(v.x, CLAMP_MIN);
                float e1 = fmaxf(v.y, CLAMP_MIN);
                float e2 = fmaxf(v.z, CLAMP_MIN);
                float e3 = fmaxf(v.w, CLAMP_MIN);
                rs[i * 2 + 0] += ex2f(fmaf(e0, wl, bl)) + ex2f(fmaf(e1, wl, bl));
                rs[i * 2 + 1] += ex2f(fmaf(e2, wl, bl)) + ex2f(fmaf(e3, wl, bl));
                if (isDiag) {
                    const int c = c0 - dOff;
                    if (r0 == c)         g_diag[rowBase + r0] = fmaf(e0, w, b);
                    if (r0 == c + 1)     g_diag[rowBase + r0] = fmaf(e1, w, b);
                    if (r0 + 8 == c)     g_diag[rowBase + r0 + 8] = fmaf(e2, w, b);
                    if (r0 + 8 == c + 1) g_diag[rowBase + r0 + 8] = fmaf(e3, w, b);
                }
            }
        }

        // ---- segment flush: only on row-block change or final tile ----
        const bool last = (t + 1 == hi);
        if (last || aSwap) {
#pragma unroll
            for (int q = 0; q < 8; q++) {
                rs[q] += __shfl_xor_sync(0xffffffffu, rs[q], 1);
                rs[q] += __shfl_xor_sync(0xffffffffu, rs[q], 2);
            }
            if (tid4 == 0) {
#pragma unroll
                for (int i = 0; i < 4; i++) {
                    int r = warp_m * 64 + i * 16 + gid;
                    red[warp_n * 128 + r] = rs[i * 2 + 0];
                    red[warp_n * 128 + r + 8] = rs[i * 2 + 1];
                }
            }
            __syncthreads();
            if (tid < 128)
                g_partF[segCt][rowBase + tid] =
                    red[tid] + red[128 + tid] + red[256 + tid] + red[384 + tid];
#pragma unroll
            for (int q = 0; q < 8; q++) rs[q] = 0.f;
            segCt = 0;   // new segment (if any) starts at ct 0 of next rb
        }

        if (t + 1 < hi) CP_WAIT0();
        __syncthreads();
        if (aSwap) { rb = (t + 1) >> 5; aCur ^= 1; }
    }
}

// ---------------------------------------------------------------------------
// Kernel 3a: per-row  log(sum of 32 slots) - diag, block-reduced -> g_blk[rb]
// ---------------------------------------------------------------------------
__global__ void __launch_bounds__(128) final1_kernel() {
    const int tid = threadIdx.x;
    const int r = blockIdx.x * 128 + tid;
    const float LN2 = 0.69314718056f;
    float sum = 0.f;
#pragma unroll
    for (int ct = 0; ct < NCT; ct++) sum += g_partF[ct][r];
    float s = lg2f(sum) * LN2 - g_diag[r];
#pragma unroll
    for (int o = 16; o; o >>= 1) s += __shfl_xor_sync(0xffffffffu, s, o);
    __shared__ float sred[4];
    if ((tid & 31) == 0) sred[tid >> 5] = s;
    __syncthreads();
    if (tid == 0) g_blk[blockIdx.x] = sred[0] + sred[1] + sred[2] + sred[3];
}

// ---------------------------------------------------------------------------
// Kernel 3b: loss = sum(g_blk) / N   (64 values, 2 warps)
// ---------------------------------------------------------------------------
__global__ void __launch_bounds__(64) final2_kernel(float* __restrict__ out) {
    const int tid = threadIdx.x;
    float s = g_blk[tid];
#pragma unroll
    for (int o = 16; o; o >>= 1) s += __shfl_xor_sync(0xffffffffu, s, o);
    __shared__ float sred[2];
    if ((tid & 31) == 0) sred[tid >> 5] = s;
    __syncthreads();
    if (tid == 0) out[0] = (sred[0] + sred[1]) * (1.0f / (float)N_SPK);
}

extern "C" void kernel_launch(void* const* d_in, const int* in_sizes, int n_in,
                              void* d_out, int out_size) {
    const float* x = (const float*)d_in[0];
    const float* w = (const float*)d_in[1];
    const float* b = (const float*)d_in[2];
    float* out = (float*)d_out;
    (void)in_sizes; (void)n_in; (void)out_size;

    cudaFuncSetAttribute(gemm_lse_kernel,
                         cudaFuncAttributeMaxDynamicSharedMemorySize, SMEM_TOTAL);

    prep_kernel<<<N_SPK / 8, 256>>>(x);
    gemm_lse_kernel<<<NCTA, GTHREADS, SMEM_TOTAL>>>(w, b);
    final1_kernel<<<NRB, 128>>>();
    final2_kernel<<<1, 64>>>(out);
}

// round 15
// speedup vs baseline: 2.6534x; 1.0066x over previous
#include <cuda_runtime.h>
#include <cuda_bf16.h>
#include <cstdint>

// ---------------- problem constants ----------------
#define N_SPK 8192
#define M_UTT 10
#define D_EMB 128
#define CLAMP_MIN 1e-6f

// ---------------- gemm tiling ----------------
#define TM 128
#define TN 256
#define NCT 32                         // col tiles per row block
#define NRB 64                         // row blocks
#define TOTAL_TILES (NRB * NCT)        // 2048
#define NCTA 148                       // one CTA per SM, one wave
#define GTHREADS 256                   // 8 warps: 2(M) x 4(N), warp tile 64x64

#define ROW_BYTES 256                  // 128 bf16
#define A_BYTES (128 * ROW_BYTES)      // 32 KB
#define B_BYTES (256 * ROW_BYTES)      // 64 KB
#define OFF_B0  (2 * A_BYTES)          // A double buffer at 0 / 32KB
#define OFF_RED (2 * A_BYTES + 2 * B_BYTES)
#define SMEM_TOTAL (OFF_RED + 2048)    // 194 KB + 2KB reduction pad

// ---------------- device scratch ----------------
__device__ __align__(16) __nv_bfloat16 g_lhat[N_SPK * D_EMB];
__device__ __align__(16) __nv_bfloat16 g_chat[N_SPK * D_EMB];
// Sparse per-segment exp-sum partials: slot = ct of the CTA-segment's first
// tile. Unwritten slots stay zero (zero-initialized at module load, never
// written); every written slot has exactly one writer per launch.
__device__ float g_partF[NCT][N_SPK];
__device__ float g_diag[N_SPK];
__device__ float g_blk[NRB];           // per-row-block partial loss sums
__device__ unsigned int g_cnt;         // last-block election counter

// ---------------- helpers ----------------
__device__ __forceinline__ uint32_t smem_u32(const void* p) {
    uint32_t a;
    asm("{ .reg .u64 t; cvta.to.shared.u64 t, %1; cvt.u32.u64 %0, t; }" : "=r"(a) : "l"(p));
    return a;
}
__device__ __forceinline__ void cp16(uint32_t dst, const void* src) {
    asm volatile("cp.async.cg.shared.global [%0], [%1], 16;" :: "r"(dst), "l"(src) : "memory");
}
#define CP_COMMIT() asm volatile("cp.async.commit_group;" ::: "memory")
#define CP_WAIT0()  asm volatile("cp.async.wait_group 0;" ::: "memory")

#define LDMX4(r0, r1, r2, r3, addr)                                            \
    asm volatile("ldmatrix.sync.aligned.m8n8.x4.shared.b16 {%0,%1,%2,%3}, [%4];" \
                 : "=r"(r0), "=r"(r1), "=r"(r2), "=r"(r3) : "r"(addr))

__device__ __forceinline__ void mma_bf16(float4& c, uint32_t a0, uint32_t a1,
                                         uint32_t a2, uint32_t a3,
                                         uint32_t b0, uint32_t b1) {
    asm volatile(
        "mma.sync.aligned.m16n8k16.row.col.f32.bf16.bf16.f32 "
        "{%0,%1,%2,%3}, {%4,%5,%6,%7}, {%8,%9}, {%0,%1,%2,%3};"
        : "+f"(c.x), "+f"(c.y), "+f"(c.z), "+f"(c.w)
        : "r"(a0), "r"(a1), "r"(a2), "r"(a3), "r"(b0), "r"(b1));
}

__device__ __forceinline__ float ex2f(float x) {
    float r; asm("ex2.approx.ftz.f32 %0, %1;" : "=f"(r) : "f"(x)); return r;
}
__device__ __forceinline__ float lg2f(float x) {
    float r; asm("lg2.approx.f32 %0, %1;" : "=f"(r) : "f"(x)); return r;
}

// ---------------------------------------------------------------------------
// Kernel 1: centroids + normalization + bf16 rounding. (DRAM-bound, ~10.5us)
// Also resets the last-block counter for this replay (safe: earlier launch).
// ---------------------------------------------------------------------------
__global__ void __launch_bounds__(256) prep_kernel(const float* __restrict__ x) {
    if (blockIdx.x == 0 && threadIdx.x == 0) g_cnt = 0;

    const int lane = threadIdx.x & 31;
    const int n = blockIdx.x * 8 + (threadIdx.x >> 5);
    const float4* xs = (const float4*)(x + (size_t)n * (M_UTT * D_EMB));

    float4 c = make_float4(0.f, 0.f, 0.f, 0.f);
    float4 l;
#pragma unroll
    for (int m = 0; m < M_UTT; m++) {
        float4 v = xs[m * 32 + lane];
        c.x += v.x; c.y += v.y; c.z += v.z; c.w += v.w;
        if (m == M_UTT - 1) l = v;
    }
    c.x *= 0.1f; c.y *= 0.1f; c.z *= 0.1f; c.w *= 0.1f;

    float sc = c.x * c.x + c.y * c.y + c.z * c.z + c.w * c.w;
    float sl = l.x * l.x + l.y * l.y + l.z * l.z + l.w * l.w;
#pragma unroll
    for (int o = 16; o; o >>= 1) {
        sc += __shfl_xor_sync(0xffffffffu, sc, o);
        sl += __shfl_xor_sync(0xffffffffu, sl, o);
    }
    const float rc = rsqrtf(sc), rl = rsqrtf(sl);

    __nv_bfloat162 c01 = __floats2bfloat162_rn(c.x * rc, c.y * rc);
    __nv_bfloat162 c23 = __floats2bfloat162_rn(c.z * rc, c.w * rc);
    __nv_bfloat162 l01 = __floats2bfloat162_rn(l.x * rl, l.y * rl);
    __nv_bfloat162 l23 = __floats2bfloat162_rn(l.z * rl, l.w * rl);

    uint2 cv, lv;
    cv.x = *(uint32_t*)&c01; cv.y = *(uint32_t*)&c23;
    lv.x = *(uint32_t*)&l01; lv.y = *(uint32_t*)&l23;
    ((uint2*)(g_chat + n * D_EMB))[lane] = cv;
    ((uint2*)(g_lhat + n * D_EMB))[lane] = lv;
}

// ---------------------------------------------------------------------------
// Kernel 2: persistent bf16 mma.sync GEMM over 148 CTAs.
// 2048 tiles (64 rb x 32 ct); CTA k owns [k*2048/148,(k+1)*2048/148).
// Row exp-sums accumulate in registers across each row-block segment and are
// flushed once per segment (2-3x per CTA) to g_partF[segment-start-ct][row].
// ---------------------------------------------------------------------------
__global__ void __launch_bounds__(GTHREADS, 1) gemm_lse_kernel(
    const float* __restrict__ wp, const float* __restrict__ bp) {
    extern __shared__ char smem[];
    const uint32_t sb = smem_u32(smem);

    const int tid = threadIdx.x;
    const int wid = tid >> 5, lane = tid & 31;
    const int warp_m = wid >> 2;          // 0..1 : 64-row stripe
    const int warp_n = wid & 3;           // 0..3 : 64-col stripe
    const int gid = lane >> 2;            // 0..7
    const int tid4 = lane & 3;

    const int bid = blockIdx.x;
    const int lo = (bid * TOTAL_TILES) / NCTA;
    const int hi = ((bid + 1) * TOTAL_TILES) / NCTA;

    const float w = *wp, b = *bp;
    const float LOG2E = 1.44269504f;
    const float wl = w * LOG2E, bl = b * LOG2E;

    const float4* A4 = (const float4*)g_lhat;
    const float4* B4 = (const float4*)g_chat;

    // ---- initial loads ----
    int rb = lo >> 5;
    {
        const int ct = lo & 31;
#pragma unroll
        for (int p = 0; p < 8; p++) {
            int idx = p * GTHREADS + tid;
            int r = idx >> 4, c = idx & 15;
            cp16(sb + (uint32_t)(r * ROW_BYTES + ((c ^ (r & 7)) << 4)),
                 &A4[(rb * TM + r) * 16 + c]);
        }
#pragma unroll
        for (int p = 0; p < 16; p++) {
            int idx = p * GTHREADS + tid;
            int r = idx >> 4, c = idx & 15;
            cp16(sb + OFF_B0 + (uint32_t)(r * ROW_BYTES + ((c ^ (r & 7)) << 4)),
                 &B4[(ct * TN + r) * 16 + c]);
        }
        CP_COMMIT();
        CP_WAIT0();
        __syncthreads();
    }

    // ---- ldmatrix lane-relative offsets ----
    uint32_t aOff[4], aSw[4];
    const int aK = lane >> 4;
#pragma unroll
    for (int i = 0; i < 4; i++) {
        int row = warp_m * 64 + i * 16 + (lane & 15);
        aOff[i] = (uint32_t)(row * ROW_BYTES);
        aSw[i] = (uint32_t)(row & 7);
    }
    uint32_t bOff[4], bSw[4];
    const int bK = (lane >> 3) & 1;
    const int nLoc = ((lane >> 4) << 3) + (lane & 7);
#pragma unroll
    for (int j2 = 0; j2 < 4; j2++) {
        int row = warp_n * 64 + j2 * 16 + nLoc;
        bOff[j2] = (uint32_t)(row * ROW_BYTES);
        bSw[j2] = (uint32_t)(row & 7);
    }

    float4 acc[4][8];
    float rs[8];
#pragma unroll
    for (int q = 0; q < 8; q++) rs[q] = 0.f;
    float* red = (float*)(smem + OFF_RED);
    int aCur = 0;
    int segCt = lo & 31;                  // g_partF slot of current segment

    for (int t = lo; t < hi; t++) {
        const int bCur = (t - lo) & 1;
        const int ct = t & 31;
        const int rowBase = rb * TM;
        const uint32_t aBuf = sb + (uint32_t)(aCur * A_BYTES);
        const uint32_t bBuf = sb + OFF_B0 + (uint32_t)(bCur * B_BYTES);

        // ---- prefetch next tile (B always; A only on row-block change) ----
        bool aSwap = false;
        if (t + 1 < hi) {
            const int rbn = (t + 1) >> 5, ctn = (t + 1) & 31;
            aSwap = (rbn != rb);
            if (aSwap) {
                const uint32_t nA = sb + (uint32_t)((aCur ^ 1) * A_BYTES);
#pragma unroll
                for (int p = 0; p < 8; p++) {
                    int idx = p * GTHREADS + tid;
                    int r = idx >> 4, c = idx & 15;
                    cp16(nA + (uint32_t)(r * ROW_BYTES + ((c ^ (r & 7)) << 4)),
                         &A4[(rbn * TM + r) * 16 + c]);
                }
            }
            const uint32_t nB = sb + OFF_B0 + (uint32_t)((bCur ^ 1) * B_BYTES);
#pragma unroll
            for (int p = 0; p < 16; p++) {
                int idx = p * GTHREADS + tid;
                int r = idx >> 4, c = idx & 15;
                cp16(nB + (uint32_t)(r * ROW_BYTES + ((c ^ (r & 7)) << 4)),
                     &B4[(ctn * TN + r) * 16 + c]);
            }
            CP_COMMIT();
        }

#pragma unroll
        for (int i = 0; i < 4; i++)
#pragma unroll
            for (int j = 0; j < 8; j++) acc[i][j] = make_float4(0.f, 0.f, 0.f, 0.f);

        // ---- k-loop: 8 steps of k=16 ----
#pragma unroll
        for (int ks = 0; ks < 8; ks++) {
            uint32_t a[4][4], bq[4][4];
#pragma unroll
            for (int i = 0; i < 4; i++) {
                uint32_t addr = aBuf + aOff[i] + ((((uint32_t)(2 * ks + aK)) ^ aSw[i]) << 4);
                LDMX4(a[i][0], a[i][1], a[i][2], a[i][3], addr);
            }
#pragma unroll
            for (int j2 = 0; j2 < 4; j2++) {
                uint32_t addr = bBuf + bOff[j2] + ((((uint32_t)(2 * ks + bK)) ^ bSw[j2]) << 4);
                LDMX4(bq[j2][0], bq[j2][1], bq[j2][2], bq[j2][3], addr);
            }
#pragma unroll
            for (int i = 0; i < 4; i++)
#pragma unroll
                for (int j = 0; j < 8; j++)
                    mma_bf16(acc[i][j], a[i][0], a[i][1], a[i][2], a[i][3],
                             bq[j >> 1][(j & 1) * 2], bq[j >> 1][(j & 1) * 2 + 1]);
        }

        // ---- epilogue: exp from registers into segment-persistent rs ----
        const bool isDiag = (ct == (rb >> 1));
        const int dOff = (rb & 1) * 128;
#pragma unroll
        for (int i = 0; i < 4; i++) {
            const int r0 = warp_m * 64 + i * 16 + gid;
#pragma unroll
            for (int j = 0; j < 8; j++) {
                const int c0 = warp_n * 64 + j * 8 + tid4 * 2;
                float4 v = acc[i][j];
                float e0 = fmaxf(v.x, CLAMP_MIN);
                float e1 = fmaxf(v.y, CLAMP_MIN);
                float e2 = fmaxf(v.z, CLAMP_MIN);
                float e3 = fmaxf(v.w, CLAMP_MIN);
                rs[i * 2 + 0] += ex2f(fmaf(e0, wl, bl)) + ex2f(fmaf(e1, wl, bl));
                rs[i * 2 + 1] += ex2f(fmaf(e2, wl, bl)) + ex2f(fmaf(e3, wl, bl));
                if (isDiag) {
                    const int c = c0 - dOff;
                    if (r0 == c)         g_diag[rowBase + r0] = fmaf(e0, w, b);
                    if (r0 == c + 1)     g_diag[rowBase + r0] = fmaf(e1, w, b);
                    if (r0 + 8 == c)     g_diag[rowBase + r0 + 8] = fmaf(e2, w, b);
                    if (r0 + 8 == c + 1) g_diag[rowBase + r0 + 8] = fmaf(e3, w, b);
                }
            }
        }

        // ---- segment flush: only on row-block change or final tile ----
        const bool last = (t + 1 == hi);
        if (last || aSwap) {
#pragma unroll
            for (int q = 0; q < 8; q++) {
                rs[q] += __shfl_xor_sync(0xffffffffu, rs[q], 1);
                rs[q] += __shfl_xor_sync(0xffffffffu, rs[q], 2);
            }
            if (tid4 == 0) {
#pragma unroll
                for (int i = 0; i < 4; i++) {
                    int r = warp_m * 64 + i * 16 + gid;
                    red[warp_n * 128 + r] = rs[i * 2 + 0];
                    red[warp_n * 128 + r + 8] = rs[i * 2 + 1];
                }
            }
            __syncthreads();
            if (tid < 128)
                g_partF[segCt][rowBase + tid] =
                    red[tid] + red[128 + tid] + red[256 + tid] + red[384 + tid];
#pragma unroll
            for (int q = 0; q < 8; q++) rs[q] = 0.f;
            segCt = 0;   // new segment (if any) starts at ct 0 of next rb
        }

        if (t + 1 < hi) {   // last tile: nothing reuses smem, skip the barrier
            CP_WAIT0();
            __syncthreads();
        }
        if (aSwap) { rb = (t + 1) >> 5; aCur ^= 1; }
    }
}

// ---------------------------------------------------------------------------
// Kernel 3: per-row  log(sum of 32 slots) - diag, block-reduced; the last
// CTA to finish (elected via g_cnt) sums the 64 block partials -> loss.
// ---------------------------------------------------------------------------
__global__ void __launch_bounds__(128) final_kernel(float* __restrict__ out) {
    const int tid = threadIdx.x;
    const int r = blockIdx.x * 128 + tid;
    const float LN2 = 0.69314718056f;
    float sum = 0.f;
#pragma unroll
    for (int ct = 0; ct < NCT; ct++) sum += g_partF[ct][r];
    float s = lg2f(sum) * LN2 - g_diag[r];
#pragma unroll
    for (int o = 16; o; o >>= 1) s += __shfl_xor_sync(0xffffffffu, s, o);
    __shared__ float sred[4];
    __shared__ int sLast;
    if ((tid & 31) == 0) sred[tid >> 5] = s;
    __syncthreads();
    if (tid == 0) {
        g_blk[blockIdx.x] = sred[0] + sred[1] + sred[2] + sred[3];
        __threadfence();
        sLast = (atomicAdd(&g_cnt, 1u) == NRB - 1);
    }
    __syncthreads();
    if (sLast && tid < 32) {
        __threadfence();   // acquire: g_blk writes of all other CTAs visible
        float v = g_blk[tid] + g_blk[tid + 32];
#pragma unroll
        for (int o = 16; o; o >>= 1) v += __shfl_xor_sync(0xffffffffu, v, o);
        if (tid == 0) out[0] = v * (1.0f / (float)N_SPK);
    }
}

extern "C" void kernel_launch(void* const* d_in, const int* in_sizes, int n_in,
                              void* d_out, int out_size) {
    const float* x = (const float*)d_in[0];
    const float* w = (const float*)d_in[1];
    const float* b = (const float*)d_in[2];
    float* out = (float*)d_out;
    (void)in_sizes; (void)n_in; (void)out_size;

    cudaFuncSetAttribute(gemm_lse_kernel,
                         cudaFuncAttributeMaxDynamicSharedMemorySize, SMEM_TOTAL);

    prep_kernel<<<N_SPK / 8, 256>>>(x);
    gemm_lse_kernel<<<NCTA, GTHREADS, SMEM_TOTAL>>>(w, b);
    final_kernel<<<NRB, 128>>>(out);
}